// round 16
// baseline (speedup 1.0000x reference)
#include <cuda_runtime.h>
#include <cuda_fp16.h>
#include <cstdint>

// ---------------------------------------------------------------------------
// Shapes (fixed by the problem instance)
#define B_   8
#define M_   8192
#define D_   1024
#define MB_  2048
#define POS  32
#define KIN  1056
#define ROWS 16384          // B_*MB_
#define KP   1088           // padded GEMM K: 1024 head + 32 ff + 32 zero

// Scratch (device globals; no allocation allowed)
__device__ __align__(256) __half g_A [(size_t)ROWS * KP];  // ~35.7 MB fp16
__device__ __align__(256) __half g_Ws[(size_t)D_   * KP];  //  ~2.2 MB fp16
__device__ int g_cnt[128];        // per-mblock pool-completion counters (0..4)

// ---------------------------------------------------------------------------
// PTX helpers (baseline sm_80 features only — compute_103-safe)
// ---------------------------------------------------------------------------
__device__ __forceinline__ uint32_t smem_u32(const void* p) {
    uint32_t a;
    asm("{ .reg .u64 t; cvta.to.shared.u64 t, %1; cvt.u32.u64 %0, t; }" : "=r"(a) : "l"(p));
    return a;
}
#define CP16(dst, src) \
    asm volatile("cp.async.cg.shared.global [%0], [%1], 16;" :: "r"(dst), "l"(src) : "memory")
#define CP_COMMIT() asm volatile("cp.async.commit_group;" ::: "memory")
#define CP_WAIT(n)  asm volatile("cp.async.wait_group %0;" :: "n"(n) : "memory")
#define NAMED_BAR(id, cnt) \
    asm volatile("bar.sync %0, %1;" :: "r"(id), "r"(cnt) : "memory")
#define LDSM4(r0, r1, r2, r3, a) \
    asm volatile("ldmatrix.sync.aligned.m8n8.x4.shared.b16 {%0,%1,%2,%3}, [%4];" \
        : "=r"(r0), "=r"(r1), "=r"(r2), "=r"(r3) : "r"(a))
#define MMA16816(d, a, b) \
    asm volatile("mma.sync.aligned.m16n8k16.row.col.f32.f16.f16.f32 " \
        "{%0,%1,%2,%3}, {%4,%5,%6,%7}, {%8,%9}, {%0,%1,%2,%3};" \
        : "+f"((d)[0]), "+f"((d)[1]), "+f"((d)[2]), "+f"((d)[3]) \
        : "r"((a)[0]), "r"((a)[1]), "r"((a)[2]), "r"((a)[3]), "r"((b)[0]), "r"((b)[1]))

#define SWZ(x) ((x) ^ (((x) >> 3) & 0x70))

__device__ __forceinline__ uint32_t pack2(float a, float b) {
    return (uint32_t)__half_as_ushort(__float2half(a)) |
           ((uint32_t)__half_as_ushort(__float2half(b)) << 16);
}

// ---------------------------------------------------------------------------
// Kernel 1: W -> fp16, cols 0..1055 from W, 1056..1087 zero.  grid = D_.
// Block 0 also zeroes the pool counters (runs before fused every replay).
// ---------------------------------------------------------------------------
__global__ __launch_bounds__(160) void wsplit_kernel(const float* __restrict__ W) {
    int o = blockIdx.x;
    int t = threadIdx.x;             // 0..159, active t < 136
    if (o == 0 && t < 128) g_cnt[t] = 0;
    if (t >= 136) return;
    uint4 v;
    if (t < 132) {
        const float* src = W + (size_t)o * KIN + t * 8;
        float4 w0 = *reinterpret_cast<const float4*>(src);
        float4 w1 = *reinterpret_cast<const float4*>(src + 4);
        v.x = pack2(w0.x, w0.y);
        v.y = pack2(w0.z, w0.w);
        v.z = pack2(w1.x, w1.y);
        v.w = pack2(w1.z, w1.w);
    } else {
        v.x = v.y = v.z = v.w = 0;
    }
    *reinterpret_cast<uint4*>(g_Ws + (size_t)o * KP + t * 8) = v;
}

// ---------------------------------------------------------------------------
// Kernel 2: FUSED warp-specialized pool + fp16 mma.sync GEMM.
// 148 CTAs (1/SM, all resident), 384 threads:
//   warps 0-7  : gemm consumer (128x128x64, 3-stage cp.async, 64x32 warp tiles)
//                tiles t = c, c+148, ... of the 128x8 tile grid
//   warps 8-11 : pool producer — units u = c, c+148, c+296, c+444 (32 rows
//                each, incl. fourier tail), flag per 128-row mblock.
// Pool streams HBM concurrently with gemm tensor work on the same SM.
// ---------------------------------------------------------------------------
#define BM 128
#define BN 128
#define BK 64
#define NKC 17               // 1088 / 64
#define NT  1024             // (16384/128) * (1024/128)
#define GRID 148
#define NUNIT 512            // pool units (32 out-rows each)
#define STAGES 3
#define TILE_B (BM * BK * 2) // 16 KB (A or B half)
#define STG_B  (2 * TILE_B)  // 32 KB per stage
#define SMEM_TOTAL (STAGES * STG_B)  // 96 KB

extern __shared__ char dynsmem[];

// pool one 32-row unit with 128 threads (pt = 0..127), incl. fourier tail
__device__ __forceinline__ void pool_unit(const float4* __restrict__ in,
                                          int u, int pt) {
    // head: 32 rows x 1024 cols mean-pool -> fp16
    #pragma unroll 4
    for (int i = 0; i < 64; ++i) {
        int idx = i * 128 + pt;          // 0..8191
        int row = u * 32 + (idx >> 8);
        int c4  = idx & 255;
        const float4* p = in + ((size_t)row * 4) * 256 + c4;
        float4 a = p[0], b = p[256], d = p[512], e = p[768];
        uint2 v;
        v.x = pack2(0.25f * (a.x + b.x + d.x + e.x), 0.25f * (a.y + b.y + d.y + e.y));
        v.y = pack2(0.25f * (a.z + b.z + d.z + e.z), 0.25f * (a.w + b.w + d.w + e.w));
        *reinterpret_cast<uint2*>(g_A + (size_t)row * KP + c4 * 4) = v;
    }
    // tail: 32 rows x 64 cols = [ff(mb) | zeros]; thread -> (row, 16-col quarter)
    {
        int rl = pt >> 2;                // 0..31 local row
        int q  = pt & 3;                 // 16-col quarter
        int row = u * 32 + rl;
        int mb  = row & (MB_ - 1);
        __half h[16];
        if (q < 2) {
            float pos = (float)mb / (float)(MB_ - 1);
            #pragma unroll
            for (int f = 0; f < 16; ++f) {
                float freq = expf((float)f * (6.907755278982137f / 15.0f));
                float ang  = pos * freq;
                h[f] = __float2half(q == 0 ? sinf(ang) : cosf(ang));
            }
        } else {
            #pragma unroll
            for (int f = 0; f < 16; ++f) h[f] = __float2half(0.0f);
        }
        uint4* dst = reinterpret_cast<uint4*>(g_A + (size_t)row * KP + 1024 + q * 16);
        dst[0] = *reinterpret_cast<uint4*>(&h[0]);
        dst[1] = *reinterpret_cast<uint4*>(&h[8]);
    }
    __threadfence();
    NAMED_BAR(2, 128);                   // pool warps only
    if (pt == 0) atomicAdd(&g_cnt[u >> 2], 1);
}

__global__ __launch_bounds__(384, 1) void fused_kernel(const float4* __restrict__ in,
                                                       float* __restrict__ C,
                                                       const float* __restrict__ bias) {
    const uint32_t sb = smem_u32(dynsmem);
    const int tid  = threadIdx.x;
    const int lane = tid & 31;
    const int c    = blockIdx.x;

    if (tid >= 256) {
        // ---------------- pool warps: stream all units ASAP -----------------
        const int pt = tid - 256;        // 0..127
        #pragma unroll
        for (int k = 0; k < 4; ++k) {
            int u = c + k * GRID;
            if (u < NUNIT) pool_unit(in, u, pt);
        }
        return;
    }

    // -------------------- gemm warps (0..7) --------------------------------
    const int wid = tid >> 5;
    const int wm  = wid >> 2;           // 0..1  (M dir, 64 rows)
    const int wn  = wid & 3;            // 0..3  (N dir, 32 cols)

    const int grow = tid >> 3;          // 0..31 base row (stride 32)
    const int gseg = tid & 7;           // 16B segment within 128B row

    uint32_t ldOff[4];
    #pragma unroll
    for (int r = 0; r < 4; ++r)
        ldOff[r] = SWZ((uint32_t)((grow + r * 32) * 128 + gseg * 16));

    uint32_t aBase[4], aSwz[4], bBase[2], bSwz[2];
    #pragma unroll
    for (int mt = 0; mt < 4; ++mt) {
        int r = wm * 64 + mt * 16 + (lane & 15);
        aBase[mt] = (uint32_t)(r * 128);
        aSwz[mt]  = (uint32_t)((r & 7) << 4);
    }
    #pragma unroll
    for (int nt2 = 0; nt2 < 2; ++nt2) {
        int r = wn * 32 + nt2 * 16 + (lane & 15);
        bBase[nt2] = (uint32_t)(r * 128);
        bSwz[nt2]  = (uint32_t)((r & 7) << 4);
    }
    const uint32_t hi16 = (lane >> 4) * 16;

    for (int t = c; t < NT; t += GRID) {
        const int mb = t >> 3;
        const int m0 = mb << 7;
        const int n0 = (t & 7) << 7;

        // wait until this tile's A rows are pooled
        if (tid == 0) {
            int v;
            do {
                asm volatile("ld.acquire.gpu.global.b32 %0, [%1];"
                             : "=r"(v) : "l"(g_cnt + mb) : "memory");
            } while (v < 4);
        }
        NAMED_BAR(1, 256);

        const __half* gA = g_A  + (size_t)(m0 + grow) * KP + gseg * 8;
        const __half* gB = g_Ws + (size_t)(n0 + grow) * KP + gseg * 8;

        float acc[4][4][4];
        #pragma unroll
        for (int i = 0; i < 4; ++i)
            #pragma unroll
            for (int j = 0; j < 4; ++j)
                #pragma unroll
                for (int v = 0; v < 4; ++v) acc[i][j][v] = 0.0f;

        // prologue: prefetch 2 chunks
        #pragma unroll
        for (int s = 0; s < STAGES - 1; ++s) {
            const uint32_t sa = sb + s * STG_B;
            #pragma unroll
            for (int r = 0; r < 4; ++r) {
                CP16(sa + ldOff[r],          gA + (size_t)(r * 32) * KP + s * 64);
                CP16(sa + TILE_B + ldOff[r], gB + (size_t)(r * 32) * KP + s * 64);
            }
            CP_COMMIT();
        }

        uint32_t afr[2][4][4], bfr[2][2][4];

        for (int kc = 0; kc < NKC; ++kc) {
            CP_WAIT(STAGES - 2);
            NAMED_BAR(1, 256);

            const int kn = kc + STAGES - 1;
            if (kn < NKC) {
                const uint32_t sa = sb + (kn % STAGES) * STG_B;
                #pragma unroll
                for (int r = 0; r < 4; ++r) {
                    CP16(sa + ldOff[r],          gA + (size_t)(r * 32) * KP + kn * 64);
                    CP16(sa + TILE_B + ldOff[r], gB + (size_t)(r * 32) * KP + kn * 64);
                }
            }
            CP_COMMIT();

            const uint32_t sA = sb + (kc % STAGES) * STG_B;
            const uint32_t sB = sA + TILE_B;

            {
                const uint32_t kb = hi16;
                #pragma unroll
                for (int mt = 0; mt < 4; ++mt)
                    LDSM4(afr[0][mt][0], afr[0][mt][1], afr[0][mt][2], afr[0][mt][3],
                          sA + aBase[mt] + (kb ^ aSwz[mt]));
                #pragma unroll
                for (int nt2 = 0; nt2 < 2; ++nt2)
                    LDSM4(bfr[0][nt2][0], bfr[0][nt2][1], bfr[0][nt2][2], bfr[0][nt2][3],
                          sB + bBase[nt2] + (kb ^ bSwz[nt2]));
            }
            #pragma unroll
            for (int ks = 0; ks < 4; ++ks) {
                const int cur = ks & 1, nxt = cur ^ 1;
                if (ks < 3) {
                    const uint32_t kb = (ks + 1) * 32 + hi16;
                    #pragma unroll
                    for (int mt = 0; mt < 4; ++mt)
                        LDSM4(afr[nxt][mt][0], afr[nxt][mt][1], afr[nxt][mt][2], afr[nxt][mt][3],
                              sA + aBase[mt] + (kb ^ aSwz[mt]));
                    #pragma unroll
                    for (int nt2 = 0; nt2 < 2; ++nt2)
                        LDSM4(bfr[nxt][nt2][0], bfr[nxt][nt2][1], bfr[nxt][nt2][2], bfr[nxt][nt2][3],
                              sB + bBase[nt2] + (kb ^ bSwz[nt2]));
                }
                #pragma unroll
                for (int mt = 0; mt < 4; ++mt) {
                    #pragma unroll
                    for (int nt = 0; nt < 4; ++nt) {
                        uint32_t bfrag[2] = { bfr[cur][nt >> 1][nt & 1],
                                              bfr[cur][nt >> 1][(nt & 1) + 2] };
                        MMA16816(acc[mt][nt], afr[cur][mt], bfrag);
                    }
                }
            }
        }

        // epilogue: + bias[col], write C
        const int group = lane >> 2;
        const int t4    = lane & 3;
        #pragma unroll
        for (int mt = 0; mt < 4; ++mt) {
            #pragma unroll
            for (int half = 0; half < 2; ++half) {
                const int row = m0 + wm * 64 + mt * 16 + group + half * 8;
                float* cp = C + (size_t)row * D_;
                #pragma unroll
                for (int nt = 0; nt < 4; ++nt) {
                    const int col = n0 + wn * 32 + nt * 8 + t4 * 2;
                    float2 bv = *reinterpret_cast<const float2*>(bias + col);
                    float2 v;
                    v.x = acc[mt][nt][half * 2]     + bv.x;
                    v.y = acc[mt][nt][half * 2 + 1] + bv.y;
                    *reinterpret_cast<float2*>(cp + col) = v;
                }
            }
        }
        NAMED_BAR(1, 256);   // smem stages reused next tile
    }
}

// ---------------------------------------------------------------------------
extern "C" void kernel_launch(void* const* d_in, const int* in_sizes, int n_in,
                              void* d_out, int out_size) {
    const float* beat = (const float*)d_in[0];   // [8, 8192, 1024]
    const float* W    = (const float*)d_in[1];   // [1024, 1056]
    const float* bias = (const float*)d_in[2];   // [1024]
    float* out = (float*)d_out;                  // [8, 2048, 1024]

    cudaFuncSetAttribute(fused_kernel, cudaFuncAttributeMaxDynamicSharedMemorySize,
                         SMEM_TOTAL);

    wsplit_kernel<<<D_, 160>>>(W);               // also zeroes g_cnt
    fused_kernel<<<GRID, 384, SMEM_TOTAL>>>((const float4*)beat, out, bias);
}